// round 8
// baseline (speedup 1.0000x reference)
#include <cuda_runtime.h>
#include <cstdint>

#define BATCH   32
#define CIN     64
#define COUT    64
#define HH      56
#define WW      56
#define LL      3136
#define FEAT    576
#define NCHUNK  18            // 576 / 32 f per chunk
#define NTHREADS 256          // 8 warps
#define NWARP   8
#define NSTAGE  16

// ---- smem layout ----
// patch: [32 b][580 floats] (tf32 bits), 2320 B rows (odd x16 -> ldsm conflict-free)
#define PROW_FLOATS 580
#define PROW_BYTES  (PROW_FLOATS * 4)          // 2320
#define PATCH_BYTES (BATCH * PROW_BYTES)       // 74240
// per-warp weight rings: 8 warps x 16 stages x [8 c][32 f] fp32 (1024 B)
#define WSTAGE_BYTES 1024
#define WRING_BYTES  (NSTAGE * WSTAGE_BYTES)   // 16384 per warp
#define WT_OFF       75776                     // PATCH_BYTES rounded up to 1KB
#define SMEM_TOTAL   (WT_OFF + NWARP * WRING_BYTES)   // 206848

// scratch: x transposed to [B][H*W][C]
__device__ float g_xt[(size_t)BATCH * LL * CIN];

// ---------------- helpers ----------------
__device__ __forceinline__ uint32_t swz(uint32_t o) { return o ^ ((o >> 3) & 0x70); }

__device__ __forceinline__ uint32_t cvt_tf32(float v) {
    uint32_t t;
    asm("cvt.rna.tf32.f32 %0, %1;" : "=r"(t) : "f"(v));
    return t;
}
__device__ __forceinline__ uint32_t tf32r(uint32_t bits) {
    uint32_t t;
    asm("cvt.rna.tf32.f32 %0, %1;" : "=r"(t) : "f"(__uint_as_float(bits)));
    return t;
}

__device__ __forceinline__ void sts32(uint32_t a, uint32_t v) {
    asm volatile("st.shared.b32 [%0], %1;" :: "r"(a), "r"(v) : "memory");
}

__device__ __forceinline__ void cp_async16(uint32_t smem_addr, const void* gmem_ptr) {
    asm volatile("cp.async.cg.shared.global [%0], [%1], 16;\n"
                 :: "r"(smem_addr), "l"(gmem_ptr));
}

__device__ __forceinline__ void ldsm_x4(uint32_t addr, uint32_t& r0, uint32_t& r1,
                                        uint32_t& r2, uint32_t& r3) {
    asm volatile("ldmatrix.sync.aligned.m8n8.x4.shared.b16 {%0,%1,%2,%3}, [%4];"
                 : "=r"(r0), "=r"(r1), "=r"(r2), "=r"(r3) : "r"(addr));
}
__device__ __forceinline__ void ldsm_x2(uint32_t addr, uint32_t& r0, uint32_t& r1) {
    asm volatile("ldmatrix.sync.aligned.m8n8.x2.shared.b16 {%0,%1}, [%2];"
                 : "=r"(r0), "=r"(r1) : "r"(addr));
}

__device__ __forceinline__ void mma_tf32(float* d, const uint32_t* a, const uint32_t* b) {
    asm volatile("mma.sync.aligned.m16n8k8.row.col.f32.tf32.tf32.f32 "
                 "{%0,%1,%2,%3}, {%4,%5,%6,%7}, {%8,%9}, {%0,%1,%2,%3};"
                 : "+f"(d[0]), "+f"(d[1]), "+f"(d[2]), "+f"(d[3])
                 : "r"(a[0]), "r"(a[1]), "r"(a[2]), "r"(a[3]),
                   "r"(b[0]), "r"(b[1]));
}

// wait until <= n cp.async groups outstanding (n must fold to a constant)
__device__ __forceinline__ void wait_groups(int n) {
    switch (n) {
        case 0:  asm volatile("cp.async.wait_group 0;\n");  break;
        case 1:  asm volatile("cp.async.wait_group 1;\n");  break;
        case 2:  asm volatile("cp.async.wait_group 2;\n");  break;
        case 3:  asm volatile("cp.async.wait_group 3;\n");  break;
        case 4:  asm volatile("cp.async.wait_group 4;\n");  break;
        case 5:  asm volatile("cp.async.wait_group 5;\n");  break;
        case 6:  asm volatile("cp.async.wait_group 6;\n");  break;
        case 7:  asm volatile("cp.async.wait_group 7;\n");  break;
        case 8:  asm volatile("cp.async.wait_group 8;\n");  break;
        case 9:  asm volatile("cp.async.wait_group 9;\n");  break;
        case 10: asm volatile("cp.async.wait_group 10;\n"); break;
        case 11: asm volatile("cp.async.wait_group 11;\n"); break;
        case 12: asm volatile("cp.async.wait_group 12;\n"); break;
        case 13: asm volatile("cp.async.wait_group 13;\n"); break;
        case 14: asm volatile("cp.async.wait_group 14;\n"); break;
        default: asm volatile("cp.async.wait_group 15;\n"); break;
    }
}

// ---------------- kernel 1: x NCHW -> NHWC transpose ----------------
__global__ void __launch_bounds__(256) transpose_x(const float* __restrict__ x) {
    __shared__ float tile[32][33];
    const int b  = blockIdx.z;
    const int c0 = blockIdx.y * 32;
    const int s0 = blockIdx.x * 32;
    const int tx = threadIdx.x & 31;
    const int ty = threadIdx.x >> 5;   // 0..7
    #pragma unroll
    for (int i = 0; i < 4; i++)
        tile[ty + 8 * i][tx] = x[((size_t)b * CIN + c0 + ty + 8 * i) * LL + s0 + tx];
    __syncthreads();
    #pragma unroll
    for (int i = 0; i < 4; i++)
        g_xt[((size_t)b * LL + s0 + ty + 8 * i) * CIN + c0 + tx] = tile[tx][ty + 8 * i];
}

// ---------------- kernel 2: per-location GEMM, deep per-warp pipeline ----------------
__global__ void __launch_bounds__(NTHREADS, 1)
lc2d_mma(const float* __restrict__ w,
         const float* __restrict__ bias,
         float* __restrict__ out)
{
    extern __shared__ char smem[];
    const uint32_t sb = (uint32_t)__cvta_generic_to_shared(smem);

    const int tid  = threadIdx.x;
    const int lane = tid & 31;
    const int warp = tid >> 5;        // 0..7, owns channels [8*warp, 8*warp+8)
    const int l    = blockIdx.x;
    const int oh   = l / WW;
    const int ow   = l - oh * WW;

    const float* wl = w + (size_t)l * (COUT * FEAT);

    // warp-private weight ring
    const uint32_t wring = sb + WT_OFF + (uint32_t)warp * WRING_BYTES;

    // cp.async mapping: lane -> row = lane>>2 (0..7), fsel = lane&3
    // per chunk: 2 instrs (j=0,1), each 8 rows x 64 B
    const int wrow = lane >> 2;
    const int fsel = lane & 3;
    const float* wg = wl + (size_t)(warp * 8 + wrow) * FEAT + 4 * fsel;   // + k*32 + j*16
    const uint32_t wsd = (uint32_t)wrow * 128 + (uint32_t)fsel * 16;      // + j*64 (pre-swz)

    // ---- prologue: issue chunks 0..14 into stages 0..14 ----
    #pragma unroll
    for (int k = 0; k < NSTAGE - 1; k++) {
        const uint32_t st = wring + (uint32_t)k * WSTAGE_BYTES;
        cp_async16(st + swz(wsd),      wg + k * 32);
        cp_async16(st + swz(wsd + 64), wg + k * 32 + 16);
        asm volatile("cp.async.commit_group;\n");
    }

    // ---- stage patches from g_xt (NHWC): segment = (b, ki, kj), 16 thr/seg ----
    {
        const int pos = tid & 15;                 // cin group: cin = pos*4 + q
        for (int s = tid >> 4; s < BATCH * 9; s += 16) {
            int b  = s / 9;
            int rr = s - b * 9;                   // ki*3 + kj
            int ki = rr / 3, kj = rr - ki * 3;
            int h  = oh + ki - 1;
            int wq = ow + kj - 1;
            bool ok = ((unsigned)h < HH) & ((unsigned)wq < WW);
            float4 v = make_float4(0.f, 0.f, 0.f, 0.f);
            if (ok)
                v = *(const float4*)(g_xt + ((size_t)b * LL + h * WW + wq) * CIN + pos * 4);
            const uint32_t prow = sb + (uint32_t)b * PROW_BYTES;
            #pragma unroll
            for (int q = 0; q < 4; q++) {
                float val = (q == 0) ? v.x : (q == 1) ? v.y : (q == 2) ? v.z : v.w;
                int f = (pos * 4 + q) * 9 + rr;
                sts32(prow + (uint32_t)f * 4, cvt_tf32(val));
            }
        }
    }

    // ---- fragment addressing ----
    // A = patches (m16 = batches): rows mt*16 + (lane&15), col half by lane&16
    const uint32_t a_row  = (uint32_t)(lane & 15);
    const uint32_t a_colq = (lane & 16) ? 16u : 0u;
    const uint32_t a_base0 = sb + a_row * PROW_BYTES + a_colq;                    // m-tile 0
    const uint32_t a_base1 = sb + (a_row + 16) * PROW_BYTES + a_colq;            // m-tile 1
    // B = weights (n8 = channels): 8 rows (lanes 0-15 give 16 addrs = 2 k-half matrices)
    const uint32_t b_off = (uint32_t)(lane & 7) * 128 + ((lane & 8) ? 16u : 0u); // + ks*32, swz

    float acc[2][4];
    #pragma unroll
    for (int mt = 0; mt < 2; mt++)
        #pragma unroll
        for (int q = 0; q < 4; q++) acc[mt][q] = 0.0f;

    __syncthreads();   // patch tile ready (only CTA-wide sync)

    // ---- main loop: fully unrolled, no barriers, deep per-warp pipeline ----
    #pragma unroll
    for (int k = 0; k < NCHUNK; k++) {
        if (k + NSTAGE - 1 < NCHUNK) {
            const uint32_t st = wring + (uint32_t)((k + NSTAGE - 1) % NSTAGE) * WSTAGE_BYTES;
            const int f0 = (k + NSTAGE - 1) * 32;
            cp_async16(st + swz(wsd),      wg + f0);
            cp_async16(st + swz(wsd + 64), wg + f0 + 16);
            asm volatile("cp.async.commit_group;\n");
        }

        // preload patch A-frags for chunk k (patch smem always ready)
        uint32_t a[2][4][4];
        #pragma unroll
        for (int ks = 0; ks < 4; ks++) {
            ldsm_x4(a_base0 + (uint32_t)(k * 128 + ks * 32),
                    a[0][ks][0], a[0][ks][1], a[0][ks][2], a[0][ks][3]);
            ldsm_x4(a_base1 + (uint32_t)(k * 128 + ks * 32),
                    a[1][ks][0], a[1][ks][1], a[1][ks][2], a[1][ks][3]);
        }

        // wait for chunk k's weights (constant after unroll)
        wait_groups((k + NSTAGE <= NCHUNK) ? (NSTAGE - 1) : (NCHUNK - 1 - k));

        const uint32_t wt = wring + (uint32_t)(k % NSTAGE) * WSTAGE_BYTES;
        #pragma unroll
        for (int ks = 0; ks < 4; ks++) {
            uint32_t bf[2];
            ldsm_x2(wt + swz(b_off + (uint32_t)ks * 32), bf[0], bf[1]);
            bf[0] = tf32r(bf[0]);
            bf[1] = tf32r(bf[1]);
            mma_tf32(acc[0], a[0][ks], bf);
            mma_tf32(acc[1], a[1][ks], bf);
        }
    }

    // ---- epilogue ----
    // D m16n8: d0=(g,2t) d1=(g,2t+1) d2=(g+8,2t) d3=(g+8,2t+1); rows=batch, cols=chan
    const int g  = lane >> 2;
    const int t2 = (lane & 3) * 2;
    const int c0 = warp * 8 + t2;
    const float* bl = bias + (size_t)l * COUT;
    const float bv0 = bl[c0];
    const float bv1 = bl[c0 + 1];
    #pragma unroll
    for (int mt = 0; mt < 2; mt++) {
        const int b0 = mt * 16 + g;
        out[((size_t)((b0    ) * COUT) + c0    ) * LL + l] = acc[mt][0] + bv0;
        out[((size_t)((b0    ) * COUT) + c0 + 1) * LL + l] = acc[mt][1] + bv1;
        out[((size_t)((b0 + 8) * COUT) + c0    ) * LL + l] = acc[mt][2] + bv0;
        out[((size_t)((b0 + 8) * COUT) + c0 + 1) * LL + l] = acc[mt][3] + bv1;
    }
}

extern "C" void kernel_launch(void* const* d_in, const int* in_sizes, int n_in,
                              void* d_out, int out_size)
{
    const float* x    = (const float*)d_in[0];   // [32,64,56,56]
    const float* w    = (const float*)d_in[1];   // [3136,64,576]
    const float* bias = (const float*)d_in[2];   // [3136,64]
    float* out        = (float*)d_out;           // [32,64,56,56]

    transpose_x<<<dim3(LL / 32, CIN / 32, BATCH), 256>>>(x);

    cudaFuncSetAttribute(lc2d_mma, cudaFuncAttributeMaxDynamicSharedMemorySize, SMEM_TOTAL);
    lc2d_mma<<<LL, NTHREADS, SMEM_TOTAL>>>(w, bias, out);
}